// round 1
// baseline (speedup 1.0000x reference)
#include <cuda_runtime.h>
#include <cstdint>

// Inverse 2D Haar DWT, fully fused elementwise butterfly.
// Inputs: LL, LH, HL, HH : [B=16, C=64, h=128, w=128] f32 (d_in[0..3]).
// Matrices (d_in[4..7]) are fixed Haar banded matrices -> folded into constants.
// Output: [B, C, 256, 256] f32.
//
// out[2i,   2j]   = 0.5*(LL - LH - HL + HH)
// out[2i,   2j+1] = 0.5*(LL + LH - HL - HH)
// out[2i+1, 2j]   = 0.5*(LL - LH + HL - HH)
// out[2i+1, 2j+1] = 0.5*(LL + LH + HL + HH)

static constexpr int H_IN  = 128;
static constexpr int W_IN  = 128;
static constexpr int PLANE_IN  = H_IN * W_IN;        // 16384
static constexpr int PLANE_OUT = 4 * PLANE_IN;       // 65536
static constexpr int W_OUT = 2 * W_IN;               // 256

// Each thread handles one float2 (2 adjacent j) of one input row
// -> writes one float4 in each of two adjacent output rows.
// threads per plane = 128 rows * 64 float2-cols = 8192
static constexpr int THREADS_PER_PLANE = H_IN * (W_IN / 2);  // 8192

__global__ void __launch_bounds__(256, 8)
idwt_haar_kernel(const float* __restrict__ LL,
                 const float* __restrict__ LH,
                 const float* __restrict__ HL,
                 const float* __restrict__ HH,
                 float* __restrict__ out)
{
    const int64_t gtid = (int64_t)blockIdx.x * blockDim.x + threadIdx.x;

    const int plane = (int)(gtid >> 13);           // / 8192
    const int rem   = (int)(gtid & 8191);
    const int row   = rem >> 6;                    // / 64  -> input row i
    const int col2  = rem & 63;                    // float2 column index

    const int64_t in_off  = (int64_t)plane * PLANE_IN + row * W_IN + col2 * 2;
    const int64_t out_off = (int64_t)plane * PLANE_OUT + (int64_t)(2 * row) * W_OUT + col2 * 4;

    const float2 a = *reinterpret_cast<const float2*>(LL + in_off);
    const float2 b = *reinterpret_cast<const float2*>(LH + in_off);
    const float2 c = *reinterpret_cast<const float2*>(HL + in_off);
    const float2 d = *reinterpret_cast<const float2*>(HH + in_off);

    float4 r0, r1;  // row 2i and row 2i+1, 4 consecutive output columns each

    // element 0 (j = 2*col2)
    {
        const float pa = a.x, pb = b.x, pc = c.x, pd = d.x;
        r0.x = 0.5f * (pa - pb - pc + pd);
        r0.y = 0.5f * (pa + pb - pc - pd);
        r1.x = 0.5f * (pa - pb + pc - pd);
        r1.y = 0.5f * (pa + pb + pc + pd);
    }
    // element 1 (j = 2*col2 + 1)
    {
        const float pa = a.y, pb = b.y, pc = c.y, pd = d.y;
        r0.z = 0.5f * (pa - pb - pc + pd);
        r0.w = 0.5f * (pa + pb - pc - pd);
        r1.z = 0.5f * (pa - pb + pc - pd);
        r1.w = 0.5f * (pa + pb + pc + pd);
    }

    *reinterpret_cast<float4*>(out + out_off)         = r0;
    *reinterpret_cast<float4*>(out + out_off + W_OUT) = r1;
}

extern "C" void kernel_launch(void* const* d_in, const int* in_sizes, int n_in,
                              void* d_out, int out_size)
{
    const float* LL = (const float*)d_in[0];
    const float* LH = (const float*)d_in[1];
    const float* HL = (const float*)d_in[2];
    const float* HH = (const float*)d_in[3];
    float* out = (float*)d_out;

    // total planes = B*C = in_sizes[0] / PLANE_IN
    const int64_t n_elems  = (int64_t)in_sizes[0];
    const int64_t planes   = n_elems / PLANE_IN;
    const int64_t nthreads = planes * THREADS_PER_PLANE;

    const int block = 256;
    const int grid  = (int)((nthreads + block - 1) / block);

    idwt_haar_kernel<<<grid, block>>>(LL, LH, HL, HH, out);
}